// round 2
// baseline (speedup 1.0000x reference)
#include <cuda_runtime.h>
#include <cuda_fp16.h>

// Problem constants (fixed by setup_inputs)
#define BATCH 4
#define NPTS  8192
#define NEDGE 262144
#define CIN   32
#define COUT  32
#define NH    16
#define TOTAL_EDGES (BATCH * NEDGE)
#define UROW  (COUT * NH)          // 512 halves per point
#define GAMMA 4.0f

// Scratch: transformed features u[b,p,o,h] in fp16 (33.5 MB, L2-resident) + W'
__device__ __align__(16) __half g_u[(size_t)BATCH * NPTS * UROW];
__device__ float g_Wt[CIN * COUT * NH];   // Wt[i][o][h] = W[h][o][i] * rsqrt(n_norm)

// ---------------------------------------------------------------------------
// Kernel 1: transpose W into [i][o][h] layout and fold in 1/sqrt(n_norm).
// ---------------------------------------------------------------------------
__global__ void k_transposeW(const float* __restrict__ W,
                             const int* __restrict__ n_norm) {
    int t = blockIdx.x * blockDim.x + threadIdx.x;   // 0..16383
    if (t >= CIN * COUT * NH) return;
    int n = *n_norm;
    float scale = (n > 0) ? rsqrtf((float)n) : 1.0f;
    int i   = t >> 9;          // /512
    int rem = t & 511;
    int o   = rem >> 4;
    int h   = rem & 15;
    g_Wt[t] = W[(h * COUT + o) * CIN + i] * scale;
}

// ---------------------------------------------------------------------------
// Kernel 2: transform  u[b,p,o,h] = sum_i Wt[i,o,h] * x[b,p,i]   (fp16 out)
// 512 threads = one (o,h) column each. PTS=32 points per block so each
// thread's 128 B W-column load is amortized over 32 points (L2 read traffic
// for g_Wt drops 268 MB -> 67 MB vs PTS=8).
// ---------------------------------------------------------------------------
#define PTS 32
__global__ __launch_bounds__(512) void k_transform(const float* __restrict__ feat) {
    __shared__ float xs[PTS * CIN];          // 4 KB
    const int t = threadIdx.x;               // 0..511  == o*16+h
    const size_t base_pt = (size_t)blockIdx.x * PTS;

    for (int i = t; i < PTS * CIN; i += 512) xs[i] = feat[base_pt * CIN + i];
    __syncthreads();

    float w[CIN];
#pragma unroll
    for (int i = 0; i < CIN; i++) w[i] = g_Wt[i * 512 + t];

    const float4* xs4 = (const float4*)xs;
    __half* uout = g_u + base_pt * UROW + t;
#pragma unroll 4
    for (int p = 0; p < PTS; p++) {
        float acc = 0.0f;
#pragma unroll
        for (int j = 0; j < CIN / 4; j++) {
            float4 xv = xs4[p * (CIN / 4) + j];
            acc = fmaf(w[4 * j + 0], xv.x, acc);
            acc = fmaf(w[4 * j + 1], xv.y, acc);
            acc = fmaf(w[4 * j + 2], xv.z, acc);
            acc = fmaf(w[4 * j + 3], xv.w, acc);
        }
        uout[(size_t)p * UROW] = __float2half_rn(acc);
    }
}

// ---------------------------------------------------------------------------
// Kernel 3: edge stage. One warp handles batches of 32 edges.
//   Metadata (src, dst, edge_vec) loaded lane-coalesced once per batch, then
//   broadcast per edge via SHFL (no per-edge scalar-load wavefronts).
//   rbf: lane h = lane&15 computes one exp; dot product pulls all 16 values
//   via SHFL.IDX (no smem round-trip -> no L1 wavefronts for the broadcast).
//   u row gathered as 2x LDG.128 per lane (1 KB coalesced, all bytes used);
//   32-lane coalesced fp32 RED scatter.
// ---------------------------------------------------------------------------
__global__ __launch_bounds__(256) void k_edges(const float* __restrict__ evec,
                                               const int*   __restrict__ esrc,
                                               const int*   __restrict__ edst,
                                               const float* __restrict__ mu,
                                               float*       __restrict__ out) {
    const int lane   = threadIdx.x & 31;
    const int gw     = (blockIdx.x * blockDim.x + threadIdx.x) >> 5;
    const int nwarps = (gridDim.x * blockDim.x) >> 5;
    const float muv  = __ldg(&mu[lane & 15]);

    for (int base = gw * 32; base < TOTAL_EDGES; base += nwarps * 32) {
        const int e = base + lane;

        // lane-coalesced metadata for 32 edges
        const int   src_v = __ldg(&esrc[e]);
        const int   dst_v = __ldg(&edst[e]);
        const float vx = __ldg(&evec[3 * (size_t)e + 0]);
        const float vy = __ldg(&evec[3 * (size_t)e + 1]);
        const float vz = __ldg(&evec[3 * (size_t)e + 2]);
        const float r_v = sqrtf(fmaf(vx, vx, fmaf(vy, vy, vz * vz)));

        // batch is 32-aligned and NEDGE % 32 == 0 -> b uniform over the batch
        const int b = base >> 18;                      // base / NEDGE
        const __half* __restrict__ ub = g_u + (size_t)(b * NPTS) * UROW;
        float* __restrict__ outb = out + (size_t)(b * NPTS) * COUT;

#pragma unroll 4
        for (int j = 0; j < 32; j++) {
            const int   src = __shfl_sync(0xffffffffu, src_v, j);
            const int   dst = __shfl_sync(0xffffffffu, dst_v, j);
            const float r   = __shfl_sync(0xffffffffu, r_v,   j);

            // start the 1 KB gather ASAP (lane = output channel)
            const uint4* up = (const uint4*)(ub + (size_t)src * UROW) + lane * 2;
            const uint4 a0 = up[0];
            const uint4 a1 = up[1];

            const float d  = r - muv;
            const float rb = __expf(-GAMMA * d * d);   // lane's h = lane & 15

            float acc = 0.0f;
            const __half2* p0 = (const __half2*)&a0;
            const __half2* p1 = (const __half2*)&a1;
#pragma unroll
            for (int h = 0; h < 8; h++) {
                const float rb0 = __shfl_sync(0xffffffffu, rb, 2 * h);
                const float rb1 = __shfl_sync(0xffffffffu, rb, 2 * h + 1);
                const float2 f  = __half22float2(h < 4 ? p0[h] : p1[h - 4]);
                acc = fmaf(rb0, f.x, fmaf(rb1, f.y, acc));
            }

            atomicAdd(&outb[(size_t)dst * COUT + lane], acc);
        }
    }
}

// ---------------------------------------------------------------------------
// Launch: memset(out) -> transposeW -> transform -> edges (default stream)
// ---------------------------------------------------------------------------
extern "C" void kernel_launch(void* const* d_in, const int* in_sizes, int n_in,
                              void* d_out, int out_size) {
    const float* features = (const float*)d_in[0];
    const float* edge_vec = (const float*)d_in[1];
    const float* W        = (const float*)d_in[2];
    const float* mu       = (const float*)d_in[3];
    const int*   edge_src = (const int*)d_in[4];
    const int*   edge_dst = (const int*)d_in[5];
    const int*   n_norm   = (const int*)d_in[6];
    float* out = (float*)d_out;

    (void)in_sizes; (void)n_in;

    cudaMemsetAsync(out, 0, (size_t)out_size * sizeof(float), 0);
    k_transposeW<<<(CIN * COUT * NH + 511) / 512, 512>>>(W, n_norm);
    k_transform<<<(BATCH * NPTS) / PTS, 512>>>(features);
    k_edges<<<148 * 8, 256>>>(edge_vec, edge_src, edge_dst, mu, out);
}

// round 3
// speedup vs baseline: 1.4092x; 1.4092x over previous
#include <cuda_runtime.h>
#include <cuda_fp16.h>

// Problem constants (fixed by setup_inputs)
#define BATCH 4
#define NPTS  8192
#define NEDGE 262144
#define CIN   32
#define COUT  32
#define NH    16
#define TOTAL_EDGES (BATCH * NEDGE)        // 1048576
#define NGROUPS (BATCH * NPTS)             // 32768 (b,src) buckets
#define UROW  (COUT * NH)                  // 512 halves per point
#define GAMMA 4.0f

// ---------------------------------------------------------------------------
// Device scratch (static; no allocations allowed)
// ---------------------------------------------------------------------------
__device__ __align__(16) __half g_u[(size_t)BATCH * NPTS * UROW];   // 33.5 MB
__device__ float g_Wt[CIN * COUT * NH];
__device__ int   g_cnt[NGROUPS];        // edges per (b,src)
__device__ int   g_cur[NGROUPS];        // scatter cursors
__device__ int   g_offs[NGROUPS];       // block-local exclusive offsets
__device__ int   g_bsum[32];            // per-scan-block totals
__device__ int   g_bbase[32];           // exclusive scan of block totals
__device__ __align__(16) float2 g_meta[TOTAL_EDGES];  // sorted (r, dst) 8 MB

// ---------------------------------------------------------------------------
// packed f32x2 helpers (FFMA2 only reachable via PTX fma.rn.f32x2)
// ---------------------------------------------------------------------------
__device__ __forceinline__ unsigned long long pack2(float x, float y) {
    unsigned long long r;
    asm("mov.b64 %0, {%1, %2};" : "=l"(r) : "f"(x), "f"(y));
    return r;
}
__device__ __forceinline__ float2 unpack2(unsigned long long p) {
    float2 f;
    asm("mov.b64 {%0, %1}, %2;" : "=f"(f.x), "=f"(f.y) : "l"(p));
    return f;
}
__device__ __forceinline__ void ffma2(unsigned long long& acc,
                                      unsigned long long a,
                                      unsigned long long b) {
    asm("fma.rn.f32x2 %0, %1, %2, %0;" : "+l"(acc) : "l"(a), "l"(b));
}

// ---------------------------------------------------------------------------
// Kernel: transpose W into [i][o][h] layout, fold in 1/sqrt(n_norm).
// ---------------------------------------------------------------------------
__global__ void k_transposeW(const float* __restrict__ W,
                             const int* __restrict__ n_norm) {
    int t = blockIdx.x * blockDim.x + threadIdx.x;
    if (t >= CIN * COUT * NH) return;
    int n = *n_norm;
    float scale = (n > 0) ? rsqrtf((float)n) : 1.0f;
    int i = t >> 9, rem = t & 511, o = rem >> 4, h = rem & 15;
    g_Wt[t] = W[(h * COUT + o) * CIN + i] * scale;
}

// ---------------------------------------------------------------------------
// Kernel: transform  u[b,p,o,h] = sum_i Wt[i,o,h] * x[b,p,i]   (fp16 out)
// ---------------------------------------------------------------------------
#define PTS 32
__global__ __launch_bounds__(512) void k_transform(const float* __restrict__ feat) {
    __shared__ float xs[PTS * CIN];
    const int t = threadIdx.x;                       // 0..511 == o*16+h
    const size_t base_pt = (size_t)blockIdx.x * PTS;

    for (int i = t; i < PTS * CIN; i += 512) xs[i] = feat[base_pt * CIN + i];
    __syncthreads();

    float w[CIN];
#pragma unroll
    for (int i = 0; i < CIN; i++) w[i] = g_Wt[i * 512 + t];

    const float4* xs4 = (const float4*)xs;
    __half* uout = g_u + base_pt * UROW + t;
#pragma unroll 4
    for (int p = 0; p < PTS; p++) {
        float acc = 0.0f;
#pragma unroll
        for (int j = 0; j < CIN / 4; j++) {
            float4 xv = xs4[p * (CIN / 4) + j];
            acc = fmaf(w[4 * j + 0], xv.x, acc);
            acc = fmaf(w[4 * j + 1], xv.y, acc);
            acc = fmaf(w[4 * j + 2], xv.z, acc);
            acc = fmaf(w[4 * j + 3], xv.w, acc);
        }
        uout[(size_t)p * UROW] = __float2half_rn(acc);
    }
}

// ---------------------------------------------------------------------------
// CSR build: zero -> histogram -> 2-level exclusive scan -> scatter (r,dst)
// ---------------------------------------------------------------------------
__global__ void k_zero() {
    int t = blockIdx.x * blockDim.x + threadIdx.x;
    if (t < NGROUPS) { g_cnt[t] = 0; g_cur[t] = 0; }
}

__global__ __launch_bounds__(256) void k_hist(const int* __restrict__ esrc) {
    int e = blockIdx.x * blockDim.x + threadIdx.x;
    if (e >= TOTAL_EDGES) return;
    int key = ((e >> 18) << 13) | __ldg(&esrc[e]);   // b*NPTS + src
    atomicAdd(&g_cnt[key], 1);
}

__global__ __launch_bounds__(1024) void k_scan1() {   // 32 blocks x 1024
    __shared__ int s[1024];
    int tid = threadIdx.x;
    int gid = blockIdx.x * 1024 + tid;
    int v = g_cnt[gid];
    s[tid] = v;
    __syncthreads();
#pragma unroll
    for (int d = 1; d < 1024; d <<= 1) {
        int t = (tid >= d) ? s[tid - d] : 0;
        __syncthreads();
        s[tid] += t;
        __syncthreads();
    }
    g_offs[gid] = s[tid] - v;                         // exclusive
    if (tid == 1023) g_bsum[blockIdx.x] = s[1023];
}

__global__ void k_scan2() {                           // 1 block x 32
    int lane = threadIdx.x;
    int v = g_bsum[lane];
    int inc = v;
#pragma unroll
    for (int d = 1; d < 32; d <<= 1) {
        int t = __shfl_up_sync(0xffffffffu, inc, d);
        if (lane >= d) inc += t;
    }
    g_bbase[lane] = inc - v;                          // exclusive
}

__global__ __launch_bounds__(256) void k_scatter(const float* __restrict__ evec,
                                                 const int* __restrict__ esrc,
                                                 const int* __restrict__ edst) {
    int e = blockIdx.x * blockDim.x + threadIdx.x;
    if (e >= TOTAL_EDGES) return;
    float vx = __ldg(&evec[3 * (size_t)e + 0]);
    float vy = __ldg(&evec[3 * (size_t)e + 1]);
    float vz = __ldg(&evec[3 * (size_t)e + 2]);
    float r = sqrtf(fmaf(vx, vx, fmaf(vy, vy, vz * vz)));
    int key = ((e >> 18) << 13) | __ldg(&esrc[e]);
    int pos = atomicAdd(&g_cur[key], 1);
    int idx = g_offs[key] + g_bbase[key >> 10] + pos;
    g_meta[idx] = make_float2(r, __int_as_float(__ldg(&edst[e])));
}

// ---------------------------------------------------------------------------
// Hot kernel: one warp per (b,src) group. u row loaded ONCE, converted once
// to 8 packed f32x2 regs. Two edges per iteration: one exp covers both
// (lanes 0-15 = h of edge0, lanes 16-31 = h of edge1); ping-pong smem
// broadcast; dot via fma.rn.f32x2; coalesced 128B RED scatter.
// ---------------------------------------------------------------------------
__global__ __launch_bounds__(256) void k_groups(const float* __restrict__ mu,
                                                float* __restrict__ out) {
    __shared__ __align__(16) float srbf[2][8][32];
    const int lane = threadIdx.x & 31;
    const int w    = threadIdx.x >> 5;
    const int g    = blockIdx.x * 8 + w;              // group id, 0..32767

    const int base = g_offs[g] + g_bbase[g >> 10];
    const int n    = g_cnt[g];
    const float muv = __ldg(&mu[lane & 15]);

    // load this source's u row: 1 KB, 2x LDG.128 per lane, convert once
    const uint4* up = (const uint4*)(g_u + (size_t)g * UROW) + lane * 2;
    const uint4 a0 = up[0];
    const uint4 a1 = up[1];
    unsigned long long uf[8];
    {
        const __half2* h0 = (const __half2*)&a0;
        const __half2* h1 = (const __half2*)&a1;
#pragma unroll
        for (int k = 0; k < 4; k++) {
            float2 f = __half22float2(h0[k]); uf[k]     = pack2(f.x, f.y);
        }
#pragma unroll
        for (int k = 0; k < 4; k++) {
            float2 f = __half22float2(h1[k]); uf[4 + k] = pack2(f.x, f.y);
        }
    }

    float* __restrict__ outb = out + (size_t)(g >> 13) * NPTS * COUT;  // b = g>>13
    int pp = 0;

    for (int j = 0; j < n; j += 2) {
        const float2 m0 = __ldg(&g_meta[base + j]);
        const bool  has1 = (j + 1 < n);
        const float2 m1 = has1 ? __ldg(&g_meta[base + j + 1]) : m0;

        const float r = (lane < 16) ? m0.x : m1.x;
        const float d = r - muv;
        srbf[pp][w][lane] = __expf(-GAMMA * d * d);
        __syncwarp();

        const ulonglong2* R = (const ulonglong2*)&srbf[pp][w][0];

        // edge 0
        unsigned long long acc0 = 0ull;
#pragma unroll
        for (int k = 0; k < 4; k++) {
            ulonglong2 rr = R[k];
            ffma2(acc0, rr.x, uf[2 * k]);
            ffma2(acc0, rr.y, uf[2 * k + 1]);
        }
        float2 f0 = unpack2(acc0);
        atomicAdd(&outb[(size_t)__float_as_int(m0.y) * COUT + lane], f0.x + f0.y);

        // edge 1
        if (has1) {
            unsigned long long acc1 = 0ull;
#pragma unroll
            for (int k = 0; k < 4; k++) {
                ulonglong2 rr = R[4 + k];
                ffma2(acc1, rr.x, uf[2 * k]);
                ffma2(acc1, rr.y, uf[2 * k + 1]);
            }
            float2 f1 = unpack2(acc1);
            atomicAdd(&outb[(size_t)__float_as_int(m1.y) * COUT + lane], f1.x + f1.y);
        }
        pp ^= 1;
    }
}

// ---------------------------------------------------------------------------
// Launch sequence (single stream, graph-capturable)
// ---------------------------------------------------------------------------
extern "C" void kernel_launch(void* const* d_in, const int* in_sizes, int n_in,
                              void* d_out, int out_size) {
    const float* features = (const float*)d_in[0];
    const float* edge_vec = (const float*)d_in[1];
    const float* W        = (const float*)d_in[2];
    const float* mu       = (const float*)d_in[3];
    const int*   edge_src = (const int*)d_in[4];
    const int*   edge_dst = (const int*)d_in[5];
    const int*   n_norm   = (const int*)d_in[6];
    float* out = (float*)d_out;

    (void)in_sizes; (void)n_in;

    cudaMemsetAsync(out, 0, (size_t)out_size * sizeof(float), 0);
    k_zero<<<(NGROUPS + 255) / 256, 256>>>();
    k_transposeW<<<(CIN * COUT * NH + 511) / 512, 512>>>(W, n_norm);
    k_hist<<<TOTAL_EDGES / 256, 256>>>(edge_src);
    k_scan1<<<32, 1024>>>();
    k_scan2<<<1, 32>>>();
    k_scatter<<<TOTAL_EDGES / 256, 256>>>(edge_vec, edge_src, edge_dst);
    k_transform<<<(BATCH * NPTS) / PTS, 512>>>(features);
    k_groups<<<NGROUPS / 8, 256>>>(mu, out);
}

// round 4
// speedup vs baseline: 1.6076x; 1.1408x over previous
#include <cuda_runtime.h>
#include <cuda_fp16.h>

// Problem constants (fixed by setup_inputs)
#define BATCH 4
#define NPTS  8192
#define NEDGE 262144
#define CIN   32
#define COUT  32
#define NH    16
#define TOTAL_EDGES (BATCH * NEDGE)        // 1048576
#define NGROUPS (BATCH * NPTS)             // 32768 (b,src) buckets
#define UROW  (COUT * NH)                  // 512 halves per point
#define GAMMA 4.0f
#define CAP   128                          // bucket capacity (Poisson(32) -> safe)
#define MAXOVF 4096

// ---------------------------------------------------------------------------
// Device scratch (static; no allocations allowed)
// ---------------------------------------------------------------------------
__device__ __align__(16) __half g_u[(size_t)BATCH * NPTS * UROW];   // 33.5 MB
__device__ float g_Wt[CIN * COUT * NH];
__device__ int   g_cnt[NGROUPS];
__device__ __align__(16) float2 g_meta[(size_t)NGROUPS * CAP];      // 33.5 MB
__device__ int   g_ovf_cnt;
__device__ int   g_ovf[MAXOVF];

// ---------------------------------------------------------------------------
// packed f32x2 helpers (FFMA2 only reachable via PTX fma.rn.f32x2)
// ---------------------------------------------------------------------------
__device__ __forceinline__ unsigned long long pack2(float x, float y) {
    unsigned long long r;
    asm("mov.b64 %0, {%1, %2};" : "=l"(r) : "f"(x), "f"(y));
    return r;
}
__device__ __forceinline__ float2 unpack2(unsigned long long p) {
    float2 f;
    asm("mov.b64 {%0, %1}, %2;" : "=f"(f.x), "=f"(f.y) : "l"(p));
    return f;
}
__device__ __forceinline__ void ffma2(unsigned long long& acc,
                                      unsigned long long a,
                                      unsigned long long b) {
    asm("fma.rn.f32x2 %0, %1, %2, %0;" : "+l"(acc) : "l"(a), "l"(b));
}

// ---------------------------------------------------------------------------
// Kernel 1: init. 256 blocks x 1024 threads = 262144 threads.
//   t < 16384 : transpose W -> Wt[i][o][h] with 1/sqrt(n_norm) folded in
//   t < 32768 : zero group counters (+ overflow counter)
//   all t     : zero one float4 of out (4 MB)
// ---------------------------------------------------------------------------
__global__ __launch_bounds__(1024) void k_init(const float* __restrict__ W,
                                               const int* __restrict__ n_norm,
                                               float* __restrict__ out) {
    const int t = blockIdx.x * 1024 + threadIdx.x;        // 0..262143
    if (t < CIN * COUT * NH) {
        int n = *n_norm;
        float scale = (n > 0) ? rsqrtf((float)n) : 1.0f;
        int i = t >> 9, rem = t & 511, o = rem >> 4, h = rem & 15;
        g_Wt[t] = W[(h * COUT + o) * CIN + i] * scale;
    }
    if (t < NGROUPS) g_cnt[t] = 0;
    if (t == 0) g_ovf_cnt = 0;
    ((float4*)out)[t] = make_float4(0.f, 0.f, 0.f, 0.f);  // 262144 float4 == 1M floats
}

// ---------------------------------------------------------------------------
// Kernel 2: fused transform + bucket build (independent block ranges).
//   blocks [0, TBLOCKS)            : u[b,p,o,h] = sum_i Wt[i,o,h]*x[b,p,i]
//   blocks [TBLOCKS, TBLOCKS+EB)   : one-pass bucket scatter of (r, dst)
// ---------------------------------------------------------------------------
#define PTS 32
#define TBLOCKS ((BATCH * NPTS) / PTS)        // 1024
#define EBLOCKS (TOTAL_EDGES / 512)           // 2048

__global__ __launch_bounds__(512) void k_fused(const float* __restrict__ feat,
                                               const float* __restrict__ evec,
                                               const int*   __restrict__ esrc,
                                               const int*   __restrict__ edst) {
    if (blockIdx.x < TBLOCKS) {
        // ---- transform ----
        __shared__ float xs[PTS * CIN];
        const int t = threadIdx.x;                       // 0..511 == o*16+h
        const size_t base_pt = (size_t)blockIdx.x * PTS;

        for (int i = t; i < PTS * CIN; i += 512) xs[i] = feat[base_pt * CIN + i];
        __syncthreads();

        float w[CIN];
#pragma unroll
        for (int i = 0; i < CIN; i++) w[i] = g_Wt[i * 512 + t];

        const float4* xs4 = (const float4*)xs;
        __half* uout = g_u + base_pt * UROW + t;
#pragma unroll 4
        for (int p = 0; p < PTS; p++) {
            float acc = 0.0f;
#pragma unroll
            for (int j = 0; j < CIN / 4; j++) {
                float4 xv = xs4[p * (CIN / 4) + j];
                acc = fmaf(w[4 * j + 0], xv.x, acc);
                acc = fmaf(w[4 * j + 1], xv.y, acc);
                acc = fmaf(w[4 * j + 2], xv.z, acc);
                acc = fmaf(w[4 * j + 3], xv.w, acc);
            }
            uout[(size_t)p * UROW] = __float2half_rn(acc);
        }
    } else {
        // ---- bucket build ----
        const int e = (blockIdx.x - TBLOCKS) * 512 + threadIdx.x;
        const float vx = __ldg(&evec[3 * (size_t)e + 0]);
        const float vy = __ldg(&evec[3 * (size_t)e + 1]);
        const float vz = __ldg(&evec[3 * (size_t)e + 2]);
        const float r = sqrtf(fmaf(vx, vx, fmaf(vy, vy, vz * vz)));
        const int key = ((e >> 18) << 13) | __ldg(&esrc[e]);  // b*NPTS + src
        const int pos = atomicAdd(&g_cnt[key], 1);
        if (pos < CAP) {
            g_meta[(size_t)key * CAP + pos] =
                make_float2(r, __int_as_float(__ldg(&edst[e])));
        } else {
            int o = atomicAdd(&g_ovf_cnt, 1);
            if (o < MAXOVF) g_ovf[o] = e;
        }
    }
}

// ---------------------------------------------------------------------------
// Kernel 3: one warp per (b,src) group. u row loaded ONCE (2x LDG.128/lane),
// converted once to 8 packed f32x2 regs. Two edges per iteration: one exp
// covers both (lanes 0-15 = h of edge0, 16-31 = edge1); meta pair via one
// LDG.128; ping-pong smem broadcast; dot via fma.rn.f32x2; coalesced RED.
// Warp (0,0) additionally drains the (expected-empty) overflow list.
// ---------------------------------------------------------------------------
__global__ __launch_bounds__(256) void k_groups(const float* __restrict__ evec,
                                                const int*   __restrict__ esrc,
                                                const int*   __restrict__ edst,
                                                const float* __restrict__ mu,
                                                float*       __restrict__ out) {
    __shared__ __align__(16) float srbf[2][8][32];
    const int lane = threadIdx.x & 31;
    const int w    = threadIdx.x >> 5;
    const int g    = blockIdx.x * 8 + w;              // group id, 0..32767

    const int n    = min(g_cnt[g], CAP);
    const float muv = __ldg(&mu[lane & 15]);

    // load this source's u row: 1 KB, 2x LDG.128 per lane, convert once
    const uint4* up = (const uint4*)(g_u + (size_t)g * UROW) + lane * 2;
    const uint4 a0 = up[0];
    const uint4 a1 = up[1];
    unsigned long long uf[8];
    {
        const __half2* h0 = (const __half2*)&a0;
        const __half2* h1 = (const __half2*)&a1;
#pragma unroll
        for (int k = 0; k < 4; k++) { float2 f = __half22float2(h0[k]); uf[k]     = pack2(f.x, f.y); }
#pragma unroll
        for (int k = 0; k < 4; k++) { float2 f = __half22float2(h1[k]); uf[4 + k] = pack2(f.x, f.y); }
    }

    const float4* __restrict__ meta4 = (const float4*)(g_meta + (size_t)g * CAP);
    float* __restrict__ outb = out + (size_t)(g >> 13) * NPTS * COUT;  // b = g>>13
    int pp = 0;

    for (int j = 0; j < n; j += 2) {
        const float4 mm = __ldg(&meta4[j >> 1]);      // (r0, dst0, r1, dst1)
        const bool has1 = (j + 1 < n);

        const float r = (lane < 16) ? mm.x : mm.z;
        const float d = r - muv;
        srbf[pp][w][lane] = __expf(-GAMMA * d * d);
        __syncwarp();

        const ulonglong2* R = (const ulonglong2*)&srbf[pp][w][0];

        unsigned long long acc0 = 0ull;
#pragma unroll
        for (int k = 0; k < 4; k++) {
            ulonglong2 rr = R[k];
            ffma2(acc0, rr.x, uf[2 * k]);
            ffma2(acc0, rr.y, uf[2 * k + 1]);
        }
        float2 f0 = unpack2(acc0);
        atomicAdd(&outb[(size_t)__float_as_int(mm.y) * COUT + lane], f0.x + f0.y);

        if (has1) {
            unsigned long long acc1 = 0ull;
#pragma unroll
            for (int k = 0; k < 4; k++) {
                ulonglong2 rr = R[4 + k];
                ffma2(acc1, rr.x, uf[2 * k]);
                ffma2(acc1, rr.y, uf[2 * k + 1]);
            }
            float2 f1 = unpack2(acc1);
            atomicAdd(&outb[(size_t)__float_as_int(mm.w) * COUT + lane], f1.x + f1.y);
        }
        pp ^= 1;
    }

    // ---- overflow fallback (expected 0 iterations) ----
    if (blockIdx.x == 0 && w == 0) {
        const int novf = min(g_ovf_cnt, MAXOVF);
        for (int t = 0; t < novf; t++) {
            const int e   = g_ovf[t];
            const int b   = e >> 18;
            const int src = esrc[e];
            const int dst = edst[e];
            const float vx = evec[3 * (size_t)e + 0];
            const float vy = evec[3 * (size_t)e + 1];
            const float vz = evec[3 * (size_t)e + 2];
            const float r  = sqrtf(fmaf(vx, vx, fmaf(vy, vy, vz * vz)));
            const float d  = r - muv;
            srbf[0][0][lane] = __expf(-GAMMA * d * d);
            __syncwarp();
            const __half* ur = g_u + ((size_t)(b * NPTS) + src) * UROW + lane * 16;
            float acc = 0.0f;
#pragma unroll
            for (int h = 0; h < 16; h++)
                acc = fmaf(srbf[0][0][h], __half2float(ur[h]), acc);
            atomicAdd(&out[((size_t)(b * NPTS) + dst) * COUT + lane], acc);
            __syncwarp();
        }
    }
}

// ---------------------------------------------------------------------------
// Launch: 3 kernels total (init -> fused transform|bucket -> groups)
// ---------------------------------------------------------------------------
extern "C" void kernel_launch(void* const* d_in, const int* in_sizes, int n_in,
                              void* d_out, int out_size) {
    const float* features = (const float*)d_in[0];
    const float* edge_vec = (const float*)d_in[1];
    const float* W        = (const float*)d_in[2];
    const float* mu       = (const float*)d_in[3];
    const int*   edge_src = (const int*)d_in[4];
    const int*   edge_dst = (const int*)d_in[5];
    const int*   n_norm   = (const int*)d_in[6];
    float* out = (float*)d_out;

    (void)in_sizes; (void)n_in; (void)out_size;

    k_init<<<256, 1024>>>(W, n_norm, out);
    k_fused<<<TBLOCKS + EBLOCKS, 512>>>(features, edge_vec, edge_src, edge_dst);
    k_groups<<<NGROUPS / 8, 256>>>(edge_vec, edge_src, edge_dst, mu, out);
}

// round 5
// speedup vs baseline: 1.7887x; 1.1127x over previous
#include <cuda_runtime.h>
#include <cuda_fp16.h>

// Problem constants (fixed by setup_inputs)
#define BATCH 4
#define NPTS  8192
#define NEDGE 262144
#define CIN   32
#define COUT  32
#define NH    16
#define TOTAL_EDGES (BATCH * NEDGE)        // 1048576
#define NGROUPS (BATCH * NPTS)             // 32768 (b,src) buckets
#define UROW  (COUT * NH)                  // 512 halves per point
#define GAMMA 4.0f
#define CAP   128                          // bucket capacity (Poisson(32) -> safe)
#define MAXOVF 4096

// ---------------------------------------------------------------------------
// Device scratch (static; no allocations allowed)
// ---------------------------------------------------------------------------
__device__ __align__(16) __half g_u[(size_t)BATCH * NPTS * UROW];   // 33.5 MB
__device__ float g_Wt[CIN * COUT * NH];
__device__ int   g_cnt[NGROUPS];
__device__ __align__(16) float2 g_meta[(size_t)NGROUPS * CAP];      // 33.5 MB
__device__ int   g_ovf_cnt;
__device__ int   g_ovf[MAXOVF];

// ---------------------------------------------------------------------------
// packed f32x2 helpers (FFMA2 only reachable via PTX fma.rn.f32x2)
// ---------------------------------------------------------------------------
__device__ __forceinline__ unsigned long long pack2(float x, float y) {
    unsigned long long r;
    asm("mov.b64 %0, {%1, %2};" : "=l"(r) : "f"(x), "f"(y));
    return r;
}
__device__ __forceinline__ float2 unpack2(unsigned long long p) {
    float2 f;
    asm("mov.b64 {%0, %1}, %2;" : "=f"(f.x), "=f"(f.y) : "l"(p));
    return f;
}
__device__ __forceinline__ void ffma2(unsigned long long& acc,
                                      unsigned long long a,
                                      unsigned long long b) {
    asm("fma.rn.f32x2 %0, %1, %2, %0;" : "+l"(acc) : "l"(a), "l"(b));
}

// ---------------------------------------------------------------------------
// Kernel 1: init. 256 blocks x 1024 threads = 262144 threads.
//   t < 16384 : transpose W -> Wt[i][o][h] with 1/sqrt(n_norm) folded in
//   t < 32768 : zero group counters (+ overflow counter)
//   all t     : zero one float4 of out (4 MB)
// ---------------------------------------------------------------------------
__global__ __launch_bounds__(1024) void k_init(const float* __restrict__ W,
                                               const int* __restrict__ n_norm,
                                               float* __restrict__ out) {
    const int t = blockIdx.x * 1024 + threadIdx.x;        // 0..262143
    if (t < CIN * COUT * NH) {
        int n = *n_norm;
        float scale = (n > 0) ? rsqrtf((float)n) : 1.0f;
        int i = t >> 9, rem = t & 511, o = rem >> 4, h = rem & 15;
        g_Wt[t] = W[(h * COUT + o) * CIN + i] * scale;
    }
    if (t < NGROUPS) g_cnt[t] = 0;
    if (t == 0) g_ovf_cnt = 0;
    ((float4*)out)[t] = make_float4(0.f, 0.f, 0.f, 0.f);  // 262144 float4 == 1M floats
}

// ---------------------------------------------------------------------------
// Kernel 2: fused transform + bucket build (independent block ranges).
//   blocks [0, TBLOCKS)          : u[b,p,o,h] = sum_i Wt[i,o,h]*x[b,p,i]
//                                  via packed fma.rn.f32x2 on POINT-PAIRS
//                                  (halves FMA-pipe slots vs scalar FFMA)
//   blocks [TBLOCKS, +EBLOCKS)   : one-pass bucket scatter of (r, dst)
// ---------------------------------------------------------------------------
#define PTS 32
#define TBLOCKS ((BATCH * NPTS) / PTS)        // 1024
#define EBLOCKS (TOTAL_EDGES / 512)           // 2048

__global__ __launch_bounds__(512) void k_fused(const float* __restrict__ feat,
                                               const float* __restrict__ evec,
                                               const int*   __restrict__ esrc,
                                               const int*   __restrict__ edst) {
    if (blockIdx.x < TBLOCKS) {
        // ---- transform (FFMA2 point-pair path) ----
        __shared__ __align__(16) unsigned long long xp[PTS / 2][CIN];  // 4 KB
        const int t = threadIdx.x;                       // 0..511 == o*16+h
        const size_t base_pt = (size_t)blockIdx.x * PTS;

        {   // pack x point-pairs: warp q packs pair (2q, 2q+1), lane = channel
            const int q = t >> 5, i = t & 31;
            const float lo = feat[(base_pt + 2 * q)     * CIN + i];
            const float hi = feat[(base_pt + 2 * q + 1) * CIN + i];
            xp[q][i] = pack2(lo, hi);                    // conflict-free STS.64
        }
        __syncthreads();

        unsigned long long w2[CIN];                      // (w,w) duplicated halves
#pragma unroll
        for (int i = 0; i < CIN; i++) {
            const float v = g_Wt[i * 512 + t];
            w2[i] = pack2(v, v);
        }

        __half* uout = g_u + base_pt * UROW + t;
#pragma unroll 2
        for (int q = 0; q < PTS / 2; q++) {
            unsigned long long acc = 0ull;
            const ulonglong2* xq = (const ulonglong2*)xp[q];   // broadcast LDS.128
#pragma unroll
            for (int j = 0; j < CIN / 2; j++) {
                const ulonglong2 xv = xq[j];
                ffma2(acc, w2[2 * j],     xv.x);
                ffma2(acc, w2[2 * j + 1], xv.y);
            }
            const float2 f = unpack2(acc);
            uout[(size_t)(2 * q)     * UROW] = __float2half_rn(f.x);
            uout[(size_t)(2 * q + 1) * UROW] = __float2half_rn(f.y);
        }
    } else {
        // ---- bucket build ----
        const int e = (blockIdx.x - TBLOCKS) * 512 + threadIdx.x;
        const float vx = __ldg(&evec[3 * (size_t)e + 0]);
        const float vy = __ldg(&evec[3 * (size_t)e + 1]);
        const float vz = __ldg(&evec[3 * (size_t)e + 2]);
        const float r = sqrtf(fmaf(vx, vx, fmaf(vy, vy, vz * vz)));
        const int key = ((e >> 18) << 13) | __ldg(&esrc[e]);  // b*NPTS + src
        const int pos = atomicAdd(&g_cnt[key], 1);
        if (pos < CAP) {
            g_meta[(size_t)key * CAP + pos] =
                make_float2(r, __int_as_float(__ldg(&edst[e])));
        } else {
            int o = atomicAdd(&g_ovf_cnt, 1);
            if (o < MAXOVF) g_ovf[o] = e;
        }
    }
}

// ---------------------------------------------------------------------------
// Kernel 3: one warp per (b,src) group. u row loaded ONCE (2x LDG.128/lane),
// converted once to 8 packed f32x2 regs. Two edges per iteration: one exp
// covers both (lanes 0-15 = h of edge0, 16-31 = edge1); meta pair via one
// LDG.128; ping-pong smem broadcast; dot via fma.rn.f32x2; coalesced RED.
// Warp (0,0) additionally drains the (expected-empty) overflow list.
// ---------------------------------------------------------------------------
__global__ __launch_bounds__(256) void k_groups(const float* __restrict__ evec,
                                                const int*   __restrict__ esrc,
                                                const int*   __restrict__ edst,
                                                const float* __restrict__ mu,
                                                float*       __restrict__ out) {
    __shared__ __align__(16) float srbf[2][8][32];
    const int lane = threadIdx.x & 31;
    const int w    = threadIdx.x >> 5;
    const int g    = blockIdx.x * 8 + w;              // group id, 0..32767

    const int n    = min(g_cnt[g], CAP);
    const float muv = __ldg(&mu[lane & 15]);

    // load this source's u row: 1 KB, 2x LDG.128 per lane, convert once
    const uint4* up = (const uint4*)(g_u + (size_t)g * UROW) + lane * 2;
    const uint4 a0 = up[0];
    const uint4 a1 = up[1];
    unsigned long long uf[8];
    {
        const __half2* h0 = (const __half2*)&a0;
        const __half2* h1 = (const __half2*)&a1;
#pragma unroll
        for (int k = 0; k < 4; k++) { float2 f = __half22float2(h0[k]); uf[k]     = pack2(f.x, f.y); }
#pragma unroll
        for (int k = 0; k < 4; k++) { float2 f = __half22float2(h1[k]); uf[4 + k] = pack2(f.x, f.y); }
    }

    const float4* __restrict__ meta4 = (const float4*)(g_meta + (size_t)g * CAP);
    float* __restrict__ outb = out + (size_t)(g >> 13) * NPTS * COUT;  // b = g>>13
    int pp = 0;

    for (int j = 0; j < n; j += 2) {
        const float4 mm = __ldg(&meta4[j >> 1]);      // (r0, dst0, r1, dst1)
        const bool has1 = (j + 1 < n);

        const float r = (lane < 16) ? mm.x : mm.z;
        const float d = r - muv;
        srbf[pp][w][lane] = __expf(-GAMMA * d * d);
        __syncwarp();

        const ulonglong2* R = (const ulonglong2*)&srbf[pp][w][0];

        unsigned long long acc0 = 0ull;
#pragma unroll
        for (int k = 0; k < 4; k++) {
            ulonglong2 rr = R[k];
            ffma2(acc0, rr.x, uf[2 * k]);
            ffma2(acc0, rr.y, uf[2 * k + 1]);
        }
        float2 f0 = unpack2(acc0);
        atomicAdd(&outb[(size_t)__float_as_int(mm.y) * COUT + lane], f0.x + f0.y);

        if (has1) {
            unsigned long long acc1 = 0ull;
#pragma unroll
            for (int k = 0; k < 4; k++) {
                ulonglong2 rr = R[4 + k];
                ffma2(acc1, rr.x, uf[2 * k]);
                ffma2(acc1, rr.y, uf[2 * k + 1]);
            }
            float2 f1 = unpack2(acc1);
            atomicAdd(&outb[(size_t)__float_as_int(mm.w) * COUT + lane], f1.x + f1.y);
        }
        pp ^= 1;
    }

    // ---- overflow fallback (expected 0 iterations) ----
    if (blockIdx.x == 0 && w == 0) {
        const int novf = min(g_ovf_cnt, MAXOVF);
        for (int t = 0; t < novf; t++) {
            const int e   = g_ovf[t];
            const int b   = e >> 18;
            const int src = esrc[e];
            const int dst = edst[e];
            const float vx = evec[3 * (size_t)e + 0];
            const float vy = evec[3 * (size_t)e + 1];
            const float vz = evec[3 * (size_t)e + 2];
            const float r  = sqrtf(fmaf(vx, vx, fmaf(vy, vy, vz * vz)));
            const float d  = r - muv;
            srbf[0][0][lane] = __expf(-GAMMA * d * d);
            __syncwarp();
            const __half* ur = g_u + ((size_t)(b * NPTS) + src) * UROW + lane * 16;
            float acc = 0.0f;
#pragma unroll
            for (int h = 0; h < 16; h++)
                acc = fmaf(srbf[0][0][h], __half2float(ur[h]), acc);
            atomicAdd(&out[((size_t)(b * NPTS) + dst) * COUT + lane], acc);
            __syncwarp();
        }
    }
}

// ---------------------------------------------------------------------------
// Launch: 3 kernels total (init -> fused transform|bucket -> groups)
// ---------------------------------------------------------------------------
extern "C" void kernel_launch(void* const* d_in, const int* in_sizes, int n_in,
                              void* d_out, int out_size) {
    const float* features = (const float*)d_in[0];
    const float* edge_vec = (const float*)d_in[1];
    const float* W        = (const float*)d_in[2];
    const float* mu       = (const float*)d_in[3];
    const int*   edge_src = (const int*)d_in[4];
    const int*   edge_dst = (const int*)d_in[5];
    const int*   n_norm   = (const int*)d_in[6];
    float* out = (float*)d_out;

    (void)in_sizes; (void)n_in; (void)out_size;

    k_init<<<256, 1024>>>(W, n_norm, out);
    k_fused<<<TBLOCKS + EBLOCKS, 512>>>(features, edge_vec, edge_src, edge_dst);
    k_groups<<<NGROUPS / 8, 256>>>(edge_vec, edge_src, edge_dst, mu, out);
}